// round 9
// baseline (speedup 1.0000x reference)
#include <cuda_runtime.h>

// ClosebyValuationFunction:
//   out[i] = (|z1[i,4]-z2[i,4]| < 2.0 && |z1[i,5]-z2[i,5]| <= 0.1) ? 0.99 : 0.01
//
// Best-measured structure (R2/R7: DRAM 83%, ~6.8 TB/s): fine-grained float2
// gather of (col4,col5) at float2 index 3i+2. Traffic is at the 436 MB
// floor (every 32B sector of both inputs is needed). Change under test:
// 2 rows per thread — MLP 2->4, stores STG.32 -> STG.64 (half the store
// requests), same benign per-warp load footprint (48 B lane stride).

__global__ __launch_bounds__(256)
void closeby_pair_kernel(const float2* __restrict__ z1,
                         const float2* __restrict__ z2,
                         float2* __restrict__ out,
                         int npair)
{
    int t = blockIdx.x * blockDim.x + threadIdx.x;
    if (t >= npair) return;

    int i0 = 2 * t;                      // first row of this pair
    int idx0 = 3 * i0 + 2;               // float2 index of (col4,col5), row i0
    int idx1 = idx0 + 3;                 // row i0+1

    float2 a0 = __ldcs(&z1[idx0]);
    float2 a1 = __ldcs(&z1[idx1]);
    float2 b0 = __ldcs(&z2[idx0]);
    float2 b1 = __ldcs(&z2[idx1]);

    float2 r;
    r.x = ((fabsf(a0.x - b0.x) < 2.0f) & (fabsf(a0.y - b0.y) <= 0.1f)) ? 0.99f : 0.01f;
    r.y = ((fabsf(a1.x - b1.x) < 2.0f) & (fabsf(a1.y - b1.y) <= 0.1f)) ? 0.99f : 0.01f;

    __stcs(&out[t], r);
}

// Tail for odd n (n = 2^23 here, so unused, but keep it general).
__global__ void closeby_tail_kernel(const float2* __restrict__ z1,
                                    const float2* __restrict__ z2,
                                    float* __restrict__ out,
                                    int start, int n)
{
    int i = start + blockIdx.x * blockDim.x + threadIdx.x;
    if (i < n) {
        int idx = 3 * i + 2;
        float2 a = __ldg(&z1[idx]);
        float2 b = __ldg(&z2[idx]);
        bool close = (fabsf(a.x - b.x) < 2.0f) & (fabsf(a.y - b.y) <= 0.1f);
        out[i] = close ? 0.99f : 0.01f;
    }
}

extern "C" void kernel_launch(void* const* d_in, const int* in_sizes, int n_in,
                              void* d_out, int out_size)
{
    const float2* z1 = (const float2*)d_in[0];
    const float2* z2 = (const float2*)d_in[1];
    int n = out_size;                    // B rows (= in_sizes[0] / 6)
    int npair = n / 2;

    if (npair > 0) {
        int threads = 256;
        int blocks = (npair + threads - 1) / threads;
        closeby_pair_kernel<<<blocks, threads>>>(z1, z2, (float2*)d_out, npair);
    }
    int tail_start = npair * 2;
    if (n - tail_start > 0) {
        closeby_tail_kernel<<<1, 32>>>(z1, z2, (float*)d_out, tail_start, n);
    }
}

// round 11
// speedup vs baseline: 1.0292x; 1.0292x over previous
#include <cuda_runtime.h>

// ClosebyValuationFunction (FINAL — settled at the chip's streaming ceiling):
//   out[i] = (|z1[i,4]-z2[i,4]| < 2.0 && |z1[i,5]-z2[i,5]| <= 0.1) ? 0.99 : 0.01
//
// One row per thread, gathered float2 of (col4,col5) at float2 index 3i+2.
// DRAM traffic is at the irreducible 436 MB floor: rows are 24 B, and
// lcm(24,32)=96 B periods touch all 3 sectors, so the full inputs must
// stream regardless of access pattern. Measured sweep (R2..R9): this
// finest-grained gather achieves 6.8 TB/s (85% of spec, DRAM 83%);
// 2-row (82%), 4-row strided (78%), and SMEM-staged (78%) variants all
// regressed — achieved BW is monotone-decreasing in per-lane gather
// stride. Evict-first hints (__ldcs/__stcs) since data has zero reuse.

__global__ __launch_bounds__(256)
void closeby_kernel(const float2* __restrict__ z1,
                    const float2* __restrict__ z2,
                    float* __restrict__ out,
                    int n)
{
    int i = blockIdx.x * blockDim.x + threadIdx.x;
    if (i < n) {
        int idx = 3 * i + 2;            // float2 index of (col4, col5) in row i
        float2 a = __ldcs(&z1[idx]);
        float2 b = __ldcs(&z2[idx]);
        float dx = fabsf(a.x - b.x);
        float dy = fabsf(a.y - b.y);
        bool close = (dx < 2.0f) & (dy <= 0.1f);
        __stcs(&out[i], close ? 0.99f : 0.01f);
    }
}

extern "C" void kernel_launch(void* const* d_in, const int* in_sizes, int n_in,
                              void* d_out, int out_size)
{
    const float2* z1 = (const float2*)d_in[0];
    const float2* z2 = (const float2*)d_in[1];
    float* out = (float*)d_out;
    int n = out_size;                   // B rows (= in_sizes[0] / 6)

    int threads = 256;
    int blocks = (n + threads - 1) / threads;
    closeby_kernel<<<blocks, threads>>>(z1, z2, out, n);
}

// round 12
// speedup vs baseline: 1.0318x; 1.0024x over previous
#include <cuda_runtime.h>

// ClosebyValuationFunction (FINAL):
//   out[i] = (|z1[i,4]-z2[i,4]| < 2.0 && |z1[i,5]-z2[i,5]| <= 0.1) ? 0.99 : 0.01
//
// One row per thread, gathered float2 of (col4,col5) at float2 index 3i+2.
// DRAM traffic is at the irreducible 436 MB floor: rows are 24 B and
// lcm(24,32)=96 B periods touch all 3 sectors, so the full inputs stream
// regardless of access pattern. Measured sweep (R2..R11):
//   24 B lane-stride gather (this):  82-84% DRAM, 6.7-6.83 TB/s  <- best
//   48 B (2 rows/thread):            82.2%
//   96 B (4 rows/thread, float4):    78.0%
//   SMEM-staged coalesced:           78.0%
// Cache-hint variants (__ldg vs __ldcs) indistinguishable within the
// ~1.5% run-to-run profile variance. This config posted the single
// highest measurement (83.5% DRAM, 6828 GB/s, 62.5 us profiled).

__global__ __launch_bounds__(256)
void closeby_kernel(const float2* __restrict__ z1,
                    const float2* __restrict__ z2,
                    float* __restrict__ out,
                    int n)
{
    int i = blockIdx.x * blockDim.x + threadIdx.x;
    if (i < n) {
        int idx = 3 * i + 2;            // float2 index of (col4, col5) in row i
        float2 a = __ldg(&z1[idx]);
        float2 b = __ldg(&z2[idx]);
        float dx = fabsf(a.x - b.x);
        float dy = fabsf(a.y - b.y);
        bool close = (dx < 2.0f) & (dy <= 0.1f);
        out[i] = close ? 0.99f : 0.01f;
    }
}

extern "C" void kernel_launch(void* const* d_in, const int* in_sizes, int n_in,
                              void* d_out, int out_size)
{
    const float2* z1 = (const float2*)d_in[0];
    const float2* z2 = (const float2*)d_in[1];
    float* out = (float*)d_out;
    int n = out_size;                   // B rows (= in_sizes[0] / 6)

    int threads = 256;
    int blocks = (n + threads - 1) / threads;
    closeby_kernel<<<blocks, threads>>>(z1, z2, out, n);
}